// round 9
// baseline (speedup 1.0000x reference)
#include <cuda_runtime.h>
#include <math.h>

#define BATCH 4
#define NA 120000
#define PRE 12000
#define POST 2000
#define CAP 16384
#define NBUCK 4096
#define IOU_T 0.7f

// ---------------- scratch (static __device__, no allocation) ----------------
__device__ float  g_scores[BATCH * NA];
__device__ float4 g_sorted[BATCH * PRE];

// ---------------- XLA:CPU GenerateVF32Exp bit-exact replica ----------------
// polynomial_approximations.cc: clamp, fx = floor(fma(x,log2e,0.5)),
// UNFUSED tmp/z mul+sub reduction, FUSED (fmuladd) Cephes Horner polynomial,
// y = fma(y,x2,x); y = 1+y; scale 2^fx via int exponent; final max(y, input).
__device__ __forceinline__ float xla_cpu_expf(float xin) {
    float xc = fminf(fmaxf(xin, -88.3762626647949f), 88.3762626647950f);
    float fx = floorf(fmaf(xc, 1.44269504088896341f, 0.5f));
    float tmp = __fmul_rn(0.693359375f, fx);
    float zz  = __fmul_rn(-2.12194440e-4f, fx);
    float x   = __fsub_rn(xc, tmp);
    x = __fsub_rn(x, zz);
    float z2 = __fmul_rn(x, x);
    float y = 1.9875691500E-4f;
    y = fmaf(y, x, 1.3981999507E-3f);
    y = fmaf(y, x, 8.3334519073E-3f);
    y = fmaf(y, x, 4.1665795894E-2f);
    y = fmaf(y, x, 1.6666665459E-1f);
    y = fmaf(y, x, 5.0000001201E-1f);
    y = fmaf(y, z2, x);
    y = __fadd_rn(1.0f, y);
    int emm0 = ((int)fx + 127) << 23;
    float scale = __int_as_float(emm0);
    return fmaxf(__fmul_rn(y, scale), xin);
}

// ---------------- K1: scores = max(softmax(labels)[1:]) ----------------
// Eager XLA:CPU semantics: e_c = vec_exp(l_c - m); sum over innermost dim 4
// is a NEON horizontal SPLIT-HALF tree reduce (VectorSupportLibrary::AddReduce):
//   s = (e0+e2) + (e1+e3)
// out = max(e1,e2,e3)/s (max commutes with division bitwise — IEEE division
// is monotone in the numerator).
__global__ void score_kernel(const float4* __restrict__ labels) {
    int i = blockIdx.x * blockDim.x + threadIdx.x;
    if (i < BATCH * NA) {
        float4 l = labels[i];
        float m = fmaxf(fmaxf(l.x, l.y), fmaxf(l.z, l.w));
        float f0 = xla_cpu_expf(__fsub_rn(l.x, m));
        float f1 = xla_cpu_expf(__fsub_rn(l.y, m));
        float f2 = xla_cpu_expf(__fsub_rn(l.z, m));
        float f3 = xla_cpu_expf(__fsub_rn(l.w, m));
        float s  = __fadd_rn(__fadd_rn(f0, f2), __fadd_rn(f1, f3));
        g_scores[i] = __fdiv_rn(fmaxf(fmaxf(f1, f2), f3), s);
    }
}

// ---------------- K2: per-batch radix-select + bitonic sort + gather ----------------
__device__ __forceinline__ void suffix_scan4096(unsigned* cnt, int tid) {
    for (int off = 1; off < NBUCK; off <<= 1) {
        unsigned v[NBUCK / 1024];
#pragma unroll
        for (int k = 0; k < NBUCK / 1024; k++) {
            int i = tid + k * 1024;
            unsigned x = cnt[i];
            if (i + off < NBUCK) x += cnt[i + off];
            v[k] = x;
        }
        __syncthreads();
#pragma unroll
        for (int k = 0; k < NBUCK / 1024; k++) cnt[tid + k * 1024] = v[k];
        __syncthreads();
    }
}

__global__ void __launch_bounds__(1024, 1) select_kernel(const float4* __restrict__ boxes) {
    extern __shared__ unsigned char smem_raw[];
    unsigned long long* sbuf = reinterpret_cast<unsigned long long*>(smem_raw);
    unsigned* cnt = reinterpret_cast<unsigned*>(smem_raw + (size_t)CAP * 8);
    __shared__ int sh_b1, sh_need, sh_b2, sh_count;

    const int b = blockIdx.x;
    const int tid = threadIdx.x;
    const int lane = tid & 31;
    const float* sc = g_scores + b * NA;
    const int NIT = (NA + 1023) / 1024;

    // ---- pass 1: histogram of top 12 bits ----
    for (int i = tid; i < NBUCK; i += 1024) cnt[i] = 0;
    __syncthreads();
    for (int it = 0; it < NIT; it++) {
        int a = it * 1024 + tid;
        unsigned bucket = 0xFFFFFFFFu;
        if (a < NA) bucket = __float_as_uint(sc[a]) >> 20;
        unsigned mask = __match_any_sync(0xFFFFFFFFu, bucket);
        int leader = __ffs(mask) - 1;
        if (bucket != 0xFFFFFFFFu && lane == leader)
            atomicAdd(&cnt[bucket], (unsigned)__popc(mask));
    }
    __syncthreads();
    suffix_scan4096(cnt, tid);
#pragma unroll
    for (int k = 0; k < NBUCK / 1024; k++) {
        int i = tid + k * 1024;
        unsigned s = cnt[i];
        unsigned nxt = (i + 1 < NBUCK) ? cnt[i + 1] : 0u;
        if (s >= PRE && nxt < PRE) { sh_b1 = i; sh_need = PRE - (int)nxt; }
    }
    __syncthreads();
    int b1 = sh_b1;
    int need = sh_need;
    __syncthreads();

    // ---- pass 2: within bucket b1, histogram of next 12 bits ----
    for (int i = tid; i < NBUCK; i += 1024) cnt[i] = 0;
    __syncthreads();
    for (int it = 0; it < NIT; it++) {
        int a = it * 1024 + tid;
        unsigned bucket = 0xFFFFFFFFu;
        if (a < NA) {
            unsigned u = __float_as_uint(sc[a]);
            if ((int)(u >> 20) == b1) bucket = (u >> 8) & 0xFFFu;
        }
        unsigned mask = __match_any_sync(0xFFFFFFFFu, bucket);
        int leader = __ffs(mask) - 1;
        if (bucket != 0xFFFFFFFFu && lane == leader)
            atomicAdd(&cnt[bucket], (unsigned)__popc(mask));
    }
    __syncthreads();
    suffix_scan4096(cnt, tid);
#pragma unroll
    for (int k = 0; k < NBUCK / 1024; k++) {
        int i = tid + k * 1024;
        unsigned s = cnt[i];
        unsigned nxt = (i + 1 < NBUCK) ? cnt[i + 1] : 0u;
        if (s >= (unsigned)need && nxt < (unsigned)need) sh_b2 = i;
    }
    if (tid == 0) sh_count = 0;
    __syncthreads();
    unsigned P = ((unsigned)b1 << 12) | (unsigned)sh_b2;

    // ---- compact all elements with (bits>>8) >= P into smem as 64-bit keys ----
    for (int it = 0; it < NIT; it++) {
        int a = it * 1024 + tid;
        if (a < NA) {
            unsigned u = __float_as_uint(sc[a]);
            if ((u >> 8) >= P) {
                int pos = atomicAdd(&sh_count, 1);
                if (pos < CAP)
                    sbuf[pos] = ((unsigned long long)u << 32) | (unsigned)(~a);
            }
        }
    }
    __syncthreads();
    int total = min(sh_count, CAP);
    for (int i = total + tid; i < CAP; i += 1024) sbuf[i] = 0ULL;
    __syncthreads();

    // ---- bitonic sort descending (CAP = 16384 u64 keys) ----
    for (unsigned k = 2; k <= CAP; k <<= 1) {
        for (unsigned j = k >> 1; j >= 1; j >>= 1) {
            for (unsigned i = tid; i < CAP; i += 1024) {
                unsigned ixj = i ^ j;
                if (ixj > i) {
                    unsigned long long va = sbuf[i], vb = sbuf[ixj];
                    bool desc = ((i & k) == 0);
                    if (desc ? (va < vb) : (va > vb)) {
                        sbuf[i] = vb;
                        sbuf[ixj] = va;
                    }
                }
            }
            __syncthreads();
        }
    }

    // ---- gather top PRE boxes ----
    const float4* bx = boxes + (size_t)b * NA;
    for (int r = tid; r < PRE; r += 1024) {
        unsigned a = ~(unsigned)(sbuf[r] & 0xFFFFFFFFu);
        g_sorted[b * PRE + r] = bx[a];
    }
}

// ---------------- IoU: reference's exact association order, no FMA ----------------
__device__ __forceinline__ float iou_f(float4 a, float4 b) {
    float iy1 = fmaxf(a.x, b.x);
    float ix1 = fmaxf(a.y, b.y);
    float iy2 = fminf(a.z, b.z);
    float ix2 = fminf(a.w, b.w);
    float ih = fmaxf(__fsub_rn(iy2, iy1), 0.f);
    float iw = fmaxf(__fsub_rn(ix2, ix1), 0.f);
    float inter = __fmul_rn(ih, iw);
    float aa = __fmul_rn(__fsub_rn(a.z, a.x), __fsub_rn(a.w, a.y));
    float ab = __fmul_rn(__fsub_rn(b.z, b.x), __fsub_rn(b.w, b.y));
    float denom = fmaxf(__fsub_rn(__fadd_rn(aa, ab), inter), 1e-8f);
    return __fdiv_rn(inter, denom);
}

// ---------------- K3: chunked lazy greedy NMS ----------------
// Proven bit-identical to the literal scan transliteration (R5 == R1/R2).
__global__ void __launch_bounds__(1024, 1) nms_kernel(float* __restrict__ out) {
    const int b = blockIdx.x;
    const int tid = threadIdx.x;
    const float4* sb = g_sorted + b * PRE;
    float* ob = out + (size_t)b * POST * 4;

    __shared__ float4 sel[POST];
    __shared__ float4 cand[32];
    __shared__ int supp[32];
    __shared__ int sh_nsel;

    if (tid == 0) sh_nsel = 0;
    __syncthreads();
    int nsel = 0;

    for (int j0 = 0; j0 < PRE && nsel < POST; j0 += 32) {
        int m = min(32, PRE - j0);
        if (tid < 32) {
            float4 c = make_float4(0.f, 0.f, 0.f, 0.f);
            if (tid < m) c = sb[j0 + tid];
            cand[tid] = c;
            supp[tid] = (tid < m) ? 0 : 1;
        }
        __syncthreads();

        // parallel phase: candidates vs all already-selected boxes
        int npairs = nsel << 5;
        for (int p = tid; p < npairs; p += 1024) {
            int c = p & 31;
            int i = p >> 5;
            if (iou_f(cand[c], sel[i]) > IOU_T) supp[c] = 1;
        }
        __syncthreads();

        // serial phase (warp 0): resolve within chunk in order
        if (tid < 32) {
            float4 myc = cand[tid];
            int mysupp = supp[tid];
            int ns = nsel;
            for (int c = 0; c < m && ns < POST; c++) {
                int csupp = __shfl_sync(0xFFFFFFFFu, mysupp, c);
                if (!csupp) {
                    float4 cb;
                    cb.x = __shfl_sync(0xFFFFFFFFu, myc.x, c);
                    cb.y = __shfl_sync(0xFFFFFFFFu, myc.y, c);
                    cb.z = __shfl_sync(0xFFFFFFFFu, myc.z, c);
                    cb.w = __shfl_sync(0xFFFFFFFFu, myc.w, c);
                    if (tid > c && !mysupp) {
                        if (iou_f(myc, cb) > IOU_T) mysupp = 1;
                    }
                    if (tid == c) {
                        sel[ns] = myc;
                        float* o = ob + ns * 4;
                        o[0] = fminf(fmaxf(myc.x, 0.f), 1.f);
                        o[1] = fminf(fmaxf(myc.y, 0.f), 1.f);
                        o[2] = fminf(fmaxf(myc.z, 0.f), 1.f);
                        o[3] = fminf(fmaxf(myc.w, 0.f), 1.f);
                    }
                    ns++;
                }
            }
            if (tid == 0) sh_nsel = ns;
        }
        __syncthreads();
        nsel = sh_nsel;
    }

    // zero-pad remaining output rows (reference pads with zeros after exhaustion)
    for (int q = tid; q < (POST - nsel) * 4; q += 1024) ob[nsel * 4 + q] = 0.f;
}

// ---------------- launcher ----------------
extern "C" void kernel_launch(void* const* d_in, const int* in_sizes, int n_in,
                              void* d_out, int out_size) {
    const float4* boxes = (const float4*)d_in[0];   // [B, A, 4] f32
    const float4* labels = (const float4*)d_in[1];  // [B, A, 4] f32
    float* out = (float*)d_out;                     // [B, POST, 4] f32

    size_t smem = (size_t)CAP * 8 + (size_t)NBUCK * 4;
    cudaFuncSetAttribute(select_kernel, cudaFuncAttributeMaxDynamicSharedMemorySize,
                         (int)smem);

    score_kernel<<<(BATCH * NA + 255) / 256, 256>>>(labels);
    select_kernel<<<BATCH, 1024, smem>>>(boxes);
    nms_kernel<<<BATCH, 1024>>>(out);
}

// round 12
// speedup vs baseline: 1.8371x; 1.8371x over previous
#include <cuda_runtime.h>
#include <math.h>

#define BATCH 4
#define NA 120000
#define PRE 12000
#define POST 2000
#define CAP 16384
#define NBUCK 4096

// ---------------- scratch (static __device__, no allocation) ----------------
__device__ float  g_scores[BATCH * NA];
__device__ float4 g_sorted[BATCH * PRE];

// ---------------- XLA:CPU GenerateVF32Exp bit-exact replica ----------------
// DO NOT TOUCH — rel_err == 0.0 with this exact arithmetic (R9).
__device__ __forceinline__ float xla_cpu_expf(float xin) {
    float xc = fminf(fmaxf(xin, -88.3762626647949f), 88.3762626647950f);
    float fx = floorf(fmaf(xc, 1.44269504088896341f, 0.5f));
    float tmp = __fmul_rn(0.693359375f, fx);
    float zz  = __fmul_rn(-2.12194440e-4f, fx);
    float x   = __fsub_rn(xc, tmp);
    x = __fsub_rn(x, zz);
    float z2 = __fmul_rn(x, x);
    float y = 1.9875691500E-4f;
    y = fmaf(y, x, 1.3981999507E-3f);
    y = fmaf(y, x, 8.3334519073E-3f);
    y = fmaf(y, x, 4.1665795894E-2f);
    y = fmaf(y, x, 1.6666665459E-1f);
    y = fmaf(y, x, 5.0000001201E-1f);
    y = fmaf(y, z2, x);
    y = __fadd_rn(1.0f, y);
    int emm0 = ((int)fx + 127) << 23;
    float scale = __int_as_float(emm0);
    return fmaxf(__fmul_rn(y, scale), xin);
}

// ---------------- K1: scores (FROZEN — bit-exact vs reference) ----------------
__global__ void score_kernel(const float4* __restrict__ labels) {
    int i = blockIdx.x * blockDim.x + threadIdx.x;
    if (i < BATCH * NA) {
        float4 l = labels[i];
        float m = fmaxf(fmaxf(l.x, l.y), fmaxf(l.z, l.w));
        float f0 = xla_cpu_expf(__fsub_rn(l.x, m));
        float f1 = xla_cpu_expf(__fsub_rn(l.y, m));
        float f2 = xla_cpu_expf(__fsub_rn(l.z, m));
        float f3 = xla_cpu_expf(__fsub_rn(l.w, m));
        float s  = __fadd_rn(__fadd_rn(f0, f2), __fadd_rn(f1, f3));
        g_scores[i] = __fdiv_rn(fmaxf(fmaxf(f1, f2), f3), s);
    }
}

// ---------------- K2: per-batch radix-select + bitonic sort + gather ----------------
__device__ __forceinline__ void suffix_scan4096(unsigned* cnt, int tid) {
    for (int off = 1; off < NBUCK; off <<= 1) {
        unsigned v[NBUCK / 1024];
#pragma unroll
        for (int k = 0; k < NBUCK / 1024; k++) {
            int i = tid + k * 1024;
            unsigned x = cnt[i];
            if (i + off < NBUCK) x += cnt[i + off];
            v[k] = x;
        }
        __syncthreads();
#pragma unroll
        for (int k = 0; k < NBUCK / 1024; k++) cnt[tid + k * 1024] = v[k];
        __syncthreads();
    }
}

#define CE64(a, b, d)                                              \
    do {                                                           \
        unsigned long long _ta = (a), _tb = (b);                   \
        if ((d) ? (_ta < _tb) : (_ta > _tb)) { (a) = _tb; (b) = _ta; } \
    } while (0)

__global__ void __launch_bounds__(1024, 1) select_kernel(const float4* __restrict__ boxes) {
    extern __shared__ unsigned char smem_raw[];
    unsigned long long* sbuf = reinterpret_cast<unsigned long long*>(smem_raw);
    unsigned* cnt = reinterpret_cast<unsigned*>(smem_raw + (size_t)CAP * 8);
    __shared__ int sh_b1, sh_need, sh_b2, sh_count;

    const int b = blockIdx.x;
    const int tid = threadIdx.x;
    const int lane = tid & 31;
    const float* sc = g_scores + b * NA;
    const int NIT = (NA + 1023) / 1024;

    // ---- pass 1: histogram of top 12 bits ----
    for (int i = tid; i < NBUCK; i += 1024) cnt[i] = 0;
    __syncthreads();
    for (int it = 0; it < NIT; it++) {
        int a = it * 1024 + tid;
        unsigned bucket = 0xFFFFFFFFu;
        if (a < NA) bucket = __float_as_uint(sc[a]) >> 20;
        unsigned mask = __match_any_sync(0xFFFFFFFFu, bucket);
        int leader = __ffs(mask) - 1;
        if (bucket != 0xFFFFFFFFu && lane == leader)
            atomicAdd(&cnt[bucket], (unsigned)__popc(mask));
    }
    __syncthreads();
    suffix_scan4096(cnt, tid);
#pragma unroll
    for (int k = 0; k < NBUCK / 1024; k++) {
        int i = tid + k * 1024;
        unsigned s = cnt[i];
        unsigned nxt = (i + 1 < NBUCK) ? cnt[i + 1] : 0u;
        if (s >= PRE && nxt < PRE) { sh_b1 = i; sh_need = PRE - (int)nxt; }
    }
    __syncthreads();
    int b1 = sh_b1;
    int need = sh_need;
    __syncthreads();

    // ---- pass 2: within bucket b1, histogram of next 12 bits ----
    for (int i = tid; i < NBUCK; i += 1024) cnt[i] = 0;
    __syncthreads();
    for (int it = 0; it < NIT; it++) {
        int a = it * 1024 + tid;
        unsigned bucket = 0xFFFFFFFFu;
        if (a < NA) {
            unsigned u = __float_as_uint(sc[a]);
            if ((int)(u >> 20) == b1) bucket = (u >> 8) & 0xFFFu;
        }
        unsigned mask = __match_any_sync(0xFFFFFFFFu, bucket);
        int leader = __ffs(mask) - 1;
        if (bucket != 0xFFFFFFFFu && lane == leader)
            atomicAdd(&cnt[bucket], (unsigned)__popc(mask));
    }
    __syncthreads();
    suffix_scan4096(cnt, tid);
#pragma unroll
    for (int k = 0; k < NBUCK / 1024; k++) {
        int i = tid + k * 1024;
        unsigned s = cnt[i];
        unsigned nxt = (i + 1 < NBUCK) ? cnt[i + 1] : 0u;
        if (s >= (unsigned)need && nxt < (unsigned)need) sh_b2 = i;
    }
    if (tid == 0) sh_count = 0;
    __syncthreads();
    unsigned P = ((unsigned)b1 << 12) | (unsigned)sh_b2;

    // ---- compact all elements with (bits>>8) >= P into smem as 64-bit keys ----
    for (int it = 0; it < NIT; it++) {
        int a = it * 1024 + tid;
        if (a < NA) {
            unsigned u = __float_as_uint(sc[a]);
            if ((u >> 8) >= P) {
                int pos = atomicAdd(&sh_count, 1);
                if (pos < CAP)
                    sbuf[pos] = ((unsigned long long)u << 32) | (unsigned)(~a);
            }
        }
    }
    __syncthreads();
    int total = min(sh_count, CAP);
    for (int i = total + tid; i < CAP; i += 1024) sbuf[i] = 0ULL;
    __syncthreads();

    // ---- bitonic sort descending, register-fused ----
    // Stage A: k=2..16 fused into one in-register pass per 16-element tile.
    // For k2<16: desc(i)=((i&k2)==0) -> (e&k2)==0 (base is 16-aligned).
    // For k2=16: desc = ((base&16)==0), tile-constant.
    {
        int base = tid * 16;
        unsigned long long v[16];
#pragma unroll
        for (int e = 0; e < 16; e++) v[e] = sbuf[base + e];
#pragma unroll
        for (int k2 = 2; k2 <= 16; k2 <<= 1) {
#pragma unroll
            for (int j = k2 >> 1; j >= 1; j >>= 1) {
#pragma unroll
                for (int e = 0; e < 16; e++) {
                    int x = e ^ j;
                    if (x > e) {
                        bool d = (k2 == 16) ? ((base & 16) == 0)
                                            : ((e & k2) == 0);
                        CE64(v[e], v[x], d);
                    }
                }
            }
        }
#pragma unroll
        for (int e = 0; e < 16; e++) sbuf[base + e] = v[e];
    }
    __syncthreads();

    // Stages k=32..CAP: j>=16 in smem, then j=8..1 fused in registers.
    for (unsigned k = 32; k <= CAP; k <<= 1) {
        for (unsigned j = k >> 1; j >= 16; j >>= 1) {
            for (unsigned i = tid; i < CAP; i += 1024) {
                unsigned ixj = i ^ j;
                if (ixj > i) {
                    unsigned long long va = sbuf[i], vb = sbuf[ixj];
                    bool d = ((i & k) == 0);
                    if (d ? (va < vb) : (va > vb)) {
                        sbuf[i] = vb;
                        sbuf[ixj] = va;
                    }
                }
            }
            __syncthreads();
        }
        {
            int base = tid * 16;
            bool d = (((unsigned)base & k) == 0);  // tile-constant for k>=32
            unsigned long long v[16];
#pragma unroll
            for (int e = 0; e < 16; e++) v[e] = sbuf[base + e];
#pragma unroll
            for (int j2 = 8; j2 >= 1; j2 >>= 1) {
#pragma unroll
                for (int e = 0; e < 16; e++) {
                    int x = e ^ j2;
                    if (x > e) CE64(v[e], v[x], d);
                }
            }
#pragma unroll
            for (int e = 0; e < 16; e++) sbuf[base + e] = v[e];
        }
        __syncthreads();
    }

    // ---- gather top PRE boxes ----
    const float4* bx = boxes + (size_t)b * NA;
    for (int r = tid; r < PRE; r += 1024) {
        unsigned a = ~(unsigned)(sbuf[r] & 0xFFFFFFFFu);
        g_sorted[b * PRE + r] = bx[a];
    }
}

// ---------------- exact IoU decision: fdiv_rn(inter,denom) > 0.7f ----------------
// 0.7f = 11744051/2^24; successor = 11744052/2^24 (even mantissa).
// div_rn(q) > 0.7f  <=>  q >= midpoint = 23488103/2^25 (tie rounds to even
// successor > 0.7f, so >= is exact). q = inter/denom with denom > 0, so
// decision <=> (double)inter >= MID * (double)denom. The f64 product of a
// 25-bit and a 24-bit value (<= 49 bits) is exact; f32->f64 is exact; the
// comparison is therefore bit-exact with the reference's rounded division.
__device__ __forceinline__ bool iou_gt(float4 a, float4 b) {
    const double MID = 23488103.0 / 33554432.0;
    float iy1 = fmaxf(a.x, b.x);
    float ix1 = fmaxf(a.y, b.y);
    float iy2 = fminf(a.z, b.z);
    float ix2 = fminf(a.w, b.w);
    float ih = fmaxf(__fsub_rn(iy2, iy1), 0.f);
    float iw = fmaxf(__fsub_rn(ix2, ix1), 0.f);
    float inter = __fmul_rn(ih, iw);
    float aa = __fmul_rn(__fsub_rn(a.z, a.x), __fsub_rn(a.w, a.y));
    float ab = __fmul_rn(__fsub_rn(b.z, b.x), __fsub_rn(b.w, b.y));
    float denom = fmaxf(__fsub_rn(__fadd_rn(aa, ab), inter), 1e-8f);
    return (double)inter >= MID * (double)denom;
}

// ---------------- K3: chunked lazy greedy NMS (ballot resolve) ----------------
// Bit-identical selection function to the literal scan transliteration
// (proven R5 == R1/R2); the in-chunk resolve now skips dead candidates via a
// live-mask + one ballot per selection instead of a 32-step shfl chain.
__global__ void __launch_bounds__(1024, 1) nms_kernel(float* __restrict__ out) {
    const int b = blockIdx.x;
    const int tid = threadIdx.x;
    const int wid = tid >> 5;
    const int lane = tid & 31;
    const float4* sb = g_sorted + b * PRE;
    float* ob = out + (size_t)b * POST * 4;

    __shared__ float4 sel[POST];
    __shared__ float4 cand[32];
    __shared__ unsigned supp_sm;
    __shared__ int sh_nsel;

    if (tid == 0) sh_nsel = 0;
    __syncthreads();
    int nsel = 0;

    for (int j0 = 0; j0 < PRE && nsel < POST; j0 += 32) {
        int m = min(32, PRE - j0);
        if (tid < 32) {
            float4 c = make_float4(0.f, 0.f, 0.f, 0.f);
            if (tid < m) c = sb[j0 + tid];
            cand[tid] = c;
        }
        if (tid == 0) supp_sm = (m < 32) ? (0xFFFFFFFFu << m) : 0u;
        __syncthreads();

        // parallel phase: lane's candidate (register) vs a warp-slice of the
        // selected list (sel[i] is a warp-broadcast load).
        {
            float4 myc = cand[lane];
            bool killed = false;
            for (int i = wid; i < nsel; i += 32) {
                float4 s = sel[i];
                if (!killed && iou_gt(myc, s)) killed = true;
            }
            unsigned kb = __ballot_sync(0xFFFFFFFFu, killed);
            if (lane == 0 && kb) atomicOr(&supp_sm, kb);
        }
        __syncthreads();

        // resolve phase (warp 0): pick lowest live, suppress later live ones.
        if (tid < 32) {
            float4 myc = cand[tid];
            unsigned live = ~supp_sm;
            int ns = nsel;
            while (live != 0u && ns < POST) {
                int c = __ffs(live) - 1;
                float4 cb;
                cb.x = __shfl_sync(0xFFFFFFFFu, myc.x, c);
                cb.y = __shfl_sync(0xFFFFFFFFu, myc.y, c);
                cb.z = __shfl_sync(0xFFFFFFFFu, myc.z, c);
                cb.w = __shfl_sync(0xFFFFFFFFu, myc.w, c);
                live &= ~(1u << c);
                bool kill = ((live >> tid) & 1u) && iou_gt(myc, cb);
                unsigned kb = __ballot_sync(0xFFFFFFFFu, kill);
                live &= ~kb;
                if (tid == 0) {
                    sel[ns] = cb;
                    float* o = ob + ns * 4;
                    o[0] = fminf(fmaxf(cb.x, 0.f), 1.f);
                    o[1] = fminf(fmaxf(cb.y, 0.f), 1.f);
                    o[2] = fminf(fmaxf(cb.z, 0.f), 1.f);
                    o[3] = fminf(fmaxf(cb.w, 0.f), 1.f);
                }
                ns++;
            }
            if (tid == 0) sh_nsel = ns;
        }
        __syncthreads();
        nsel = sh_nsel;
    }

    // zero-pad remaining output rows
    for (int q = tid; q < (POST - nsel) * 4; q += 1024) ob[nsel * 4 + q] = 0.f;
}

// ---------------- launcher ----------------
extern "C" void kernel_launch(void* const* d_in, const int* in_sizes, int n_in,
                              void* d_out, int out_size) {
    const float4* boxes = (const float4*)d_in[0];   // [B, A, 4] f32
    const float4* labels = (const float4*)d_in[1];  // [B, A, 4] f32
    float* out = (float*)d_out;                     // [B, POST, 4] f32

    size_t smem = (size_t)CAP * 8 + (size_t)NBUCK * 4;
    cudaFuncSetAttribute(select_kernel, cudaFuncAttributeMaxDynamicSharedMemorySize,
                         (int)smem);

    score_kernel<<<(BATCH * NA + 255) / 256, 256>>>(labels);
    select_kernel<<<BATCH, 1024, smem>>>(boxes);
    nms_kernel<<<BATCH, 1024>>>(out);
}

// round 13
// speedup vs baseline: 2.1025x; 1.1444x over previous
#include <cuda_runtime.h>
#include <math.h>

#define BATCH 4
#define NA 120000
#define PRE 12000
#define POST 2000
#define CAP 16384
#define PCAP (CAP + CAP / 16)          // padded physical size (17-stride tiles)
#define PHYS(i) ((i) + ((i) >> 4))     // logical -> physical index (u64 slots)
#define NBUCK 4096

// ---------------- scratch (static __device__, no allocation) ----------------
__device__ float  g_scores[BATCH * NA];
__device__ float4 g_sorted[BATCH * PRE];

// ---------------- XLA:CPU GenerateVF32Exp bit-exact replica ----------------
// DO NOT TOUCH — rel_err == 0.0 with this exact arithmetic (R9/R12).
__device__ __forceinline__ float xla_cpu_expf(float xin) {
    float xc = fminf(fmaxf(xin, -88.3762626647949f), 88.3762626647950f);
    float fx = floorf(fmaf(xc, 1.44269504088896341f, 0.5f));
    float tmp = __fmul_rn(0.693359375f, fx);
    float zz  = __fmul_rn(-2.12194440e-4f, fx);
    float x   = __fsub_rn(xc, tmp);
    x = __fsub_rn(x, zz);
    float z2 = __fmul_rn(x, x);
    float y = 1.9875691500E-4f;
    y = fmaf(y, x, 1.3981999507E-3f);
    y = fmaf(y, x, 8.3334519073E-3f);
    y = fmaf(y, x, 4.1665795894E-2f);
    y = fmaf(y, x, 1.6666665459E-1f);
    y = fmaf(y, x, 5.0000001201E-1f);
    y = fmaf(y, z2, x);
    y = __fadd_rn(1.0f, y);
    int emm0 = ((int)fx + 127) << 23;
    float scale = __int_as_float(emm0);
    return fmaxf(__fmul_rn(y, scale), xin);
}

// ---------------- K1: scores (FROZEN — bit-exact vs reference) ----------------
__global__ void score_kernel(const float4* __restrict__ labels) {
    int i = blockIdx.x * blockDim.x + threadIdx.x;
    if (i < BATCH * NA) {
        float4 l = labels[i];
        float m = fmaxf(fmaxf(l.x, l.y), fmaxf(l.z, l.w));
        float f0 = xla_cpu_expf(__fsub_rn(l.x, m));
        float f1 = xla_cpu_expf(__fsub_rn(l.y, m));
        float f2 = xla_cpu_expf(__fsub_rn(l.z, m));
        float f3 = xla_cpu_expf(__fsub_rn(l.w, m));
        float s  = __fadd_rn(__fadd_rn(f0, f2), __fadd_rn(f1, f3));
        g_scores[i] = __fdiv_rn(fmaxf(fmaxf(f1, f2), f3), s);
    }
}

// ---------------- K2: per-batch radix-select + bitonic sort + gather ----------------
__device__ __forceinline__ void suffix_scan4096(unsigned* cnt, int tid) {
    for (int off = 1; off < NBUCK; off <<= 1) {
        unsigned v[NBUCK / 1024];
#pragma unroll
        for (int k = 0; k < NBUCK / 1024; k++) {
            int i = tid + k * 1024;
            unsigned x = cnt[i];
            if (i + off < NBUCK) x += cnt[i + off];
            v[k] = x;
        }
        __syncthreads();
#pragma unroll
        for (int k = 0; k < NBUCK / 1024; k++) cnt[tid + k * 1024] = v[k];
        __syncthreads();
    }
}

#define CE64(a, b, d)                                              \
    do {                                                           \
        unsigned long long _ta = (a), _tb = (b);                   \
        if ((d) ? (_ta < _tb) : (_ta > _tb)) { (a) = _tb; (b) = _ta; } \
    } while (0)

__global__ void __launch_bounds__(1024, 1) select_kernel(const float4* __restrict__ boxes) {
    extern __shared__ unsigned char smem_raw[];
    unsigned long long* sbuf = reinterpret_cast<unsigned long long*>(smem_raw);
    unsigned* cnt = reinterpret_cast<unsigned*>(smem_raw + (size_t)PCAP * 8);
    __shared__ int sh_b1, sh_need, sh_b2, sh_count;

    const int b = blockIdx.x;
    const int tid = threadIdx.x;
    const int lane = tid & 31;
    const float* sc = g_scores + b * NA;
    const int NIT = (NA + 1023) / 1024;

    // ---- pass 1: histogram of top 12 bits ----
    for (int i = tid; i < NBUCK; i += 1024) cnt[i] = 0;
    __syncthreads();
    for (int it = 0; it < NIT; it++) {
        int a = it * 1024 + tid;
        unsigned bucket = 0xFFFFFFFFu;
        if (a < NA) bucket = __float_as_uint(sc[a]) >> 20;
        unsigned mask = __match_any_sync(0xFFFFFFFFu, bucket);
        int leader = __ffs(mask) - 1;
        if (bucket != 0xFFFFFFFFu && lane == leader)
            atomicAdd(&cnt[bucket], (unsigned)__popc(mask));
    }
    __syncthreads();
    suffix_scan4096(cnt, tid);
#pragma unroll
    for (int k = 0; k < NBUCK / 1024; k++) {
        int i = tid + k * 1024;
        unsigned s = cnt[i];
        unsigned nxt = (i + 1 < NBUCK) ? cnt[i + 1] : 0u;
        if (s >= PRE && nxt < PRE) { sh_b1 = i; sh_need = PRE - (int)nxt; }
    }
    __syncthreads();
    int b1 = sh_b1;
    int need = sh_need;
    __syncthreads();

    // ---- pass 2: within bucket b1, histogram of next 12 bits ----
    for (int i = tid; i < NBUCK; i += 1024) cnt[i] = 0;
    __syncthreads();
    for (int it = 0; it < NIT; it++) {
        int a = it * 1024 + tid;
        unsigned bucket = 0xFFFFFFFFu;
        if (a < NA) {
            unsigned u = __float_as_uint(sc[a]);
            if ((int)(u >> 20) == b1) bucket = (u >> 8) & 0xFFFu;
        }
        unsigned mask = __match_any_sync(0xFFFFFFFFu, bucket);
        int leader = __ffs(mask) - 1;
        if (bucket != 0xFFFFFFFFu && lane == leader)
            atomicAdd(&cnt[bucket], (unsigned)__popc(mask));
    }
    __syncthreads();
    suffix_scan4096(cnt, tid);
#pragma unroll
    for (int k = 0; k < NBUCK / 1024; k++) {
        int i = tid + k * 1024;
        unsigned s = cnt[i];
        unsigned nxt = (i + 1 < NBUCK) ? cnt[i + 1] : 0u;
        if (s >= (unsigned)need && nxt < (unsigned)need) sh_b2 = i;
    }
    if (tid == 0) sh_count = 0;
    __syncthreads();
    unsigned P = ((unsigned)b1 << 12) | (unsigned)sh_b2;

    // ---- compact survivors into padded smem as 64-bit keys (warp-aggregated) ----
    // Order of insertion is irrelevant: keys are unique, sort output invariant.
    for (int it = 0; it < NIT; it++) {
        int a = it * 1024 + tid;
        unsigned u = 0;
        bool keep = false;
        if (a < NA) {
            u = __float_as_uint(sc[a]);
            keep = ((u >> 8) >= P);
        }
        unsigned bm = __ballot_sync(0xFFFFFFFFu, keep);
        if (keep) {
            int leader = __ffs(bm) - 1;
            int base;
            if (lane == leader) base = atomicAdd(&sh_count, __popc(bm));
            base = __shfl_sync(bm, base, leader);
            int pos = base + __popc(bm & ((1u << lane) - 1u));
            if (pos < CAP)
                sbuf[PHYS(pos)] = ((unsigned long long)u << 32) | (unsigned)(~a);
        }
    }
    __syncthreads();
    int total = min(sh_count, CAP);
    for (int i = total + tid; i < CAP; i += 1024) sbuf[PHYS(i)] = 0ULL;
    __syncthreads();

    // ---- bitonic sort descending, register-fused, bank-conflict-free tiles ----
    // Logical tile [16t, 16t+16) lives at phys [17t, 17t+16) (contiguous).
    {
        int base = tid * 16;        // logical
        int pbase = 17 * tid;       // physical
        unsigned long long v[16];
#pragma unroll
        for (int e = 0; e < 16; e++) v[e] = sbuf[pbase + e];
#pragma unroll
        for (int k2 = 2; k2 <= 16; k2 <<= 1) {
#pragma unroll
            for (int j = k2 >> 1; j >= 1; j >>= 1) {
#pragma unroll
                for (int e = 0; e < 16; e++) {
                    int x = e ^ j;
                    if (x > e) {
                        bool d = (k2 == 16) ? ((base & 16) == 0)
                                            : ((e & k2) == 0);
                        CE64(v[e], v[x], d);
                    }
                }
            }
        }
#pragma unroll
        for (int e = 0; e < 16; e++) sbuf[pbase + e] = v[e];
    }
    __syncthreads();

    // Stages k=32..CAP: j>=16 in smem (phys addressing), then j=8..1 fused.
    for (unsigned k = 32; k <= CAP; k <<= 1) {
        for (unsigned j = k >> 1; j >= 16; j >>= 1) {
            for (unsigned i = tid; i < CAP; i += 1024) {
                unsigned ixj = i ^ j;
                if (ixj > i) {
                    unsigned pi = PHYS(i), pj = PHYS(ixj);
                    unsigned long long va = sbuf[pi], vb = sbuf[pj];
                    bool d = ((i & k) == 0);
                    if (d ? (va < vb) : (va > vb)) {
                        sbuf[pi] = vb;
                        sbuf[pj] = va;
                    }
                }
            }
            __syncthreads();
        }
        {
            int base = tid * 16;
            int pbase = 17 * tid;
            bool d = (((unsigned)base & k) == 0);  // tile-constant for k>=32
            unsigned long long v[16];
#pragma unroll
            for (int e = 0; e < 16; e++) v[e] = sbuf[pbase + e];
#pragma unroll
            for (int j2 = 8; j2 >= 1; j2 >>= 1) {
#pragma unroll
                for (int e = 0; e < 16; e++) {
                    int x = e ^ j2;
                    if (x > e) CE64(v[e], v[x], d);
                }
            }
#pragma unroll
            for (int e = 0; e < 16; e++) sbuf[pbase + e] = v[e];
        }
        __syncthreads();
    }

    // ---- gather top PRE boxes ----
    const float4* bx = boxes + (size_t)b * NA;
    for (int r = tid; r < PRE; r += 1024) {
        unsigned a = ~(unsigned)(sbuf[PHYS(r)] & 0xFFFFFFFFu);
        g_sorted[b * PRE + r] = bx[a];
    }
}

// ---------------- exact IoU decision: fdiv_rn(inter,denom) > 0.7f ----------------
// div_rn(q) > 0.7f  <=>  q >= midpoint(0.7f, succ) = 23488103/2^25 (tie rounds
// to even successor > 0.7f). denom > 0, so decision <=> (double)inter >=
// MID * (double)denom; the 25x24-bit f64 product is exact => bit-exact.
__device__ __forceinline__ bool iou_gt(float4 a, float4 b) {
    const double MID = 23488103.0 / 33554432.0;
    float iy1 = fmaxf(a.x, b.x);
    float ix1 = fmaxf(a.y, b.y);
    float iy2 = fminf(a.z, b.z);
    float ix2 = fminf(a.w, b.w);
    float ih = fmaxf(__fsub_rn(iy2, iy1), 0.f);
    float iw = fmaxf(__fsub_rn(ix2, ix1), 0.f);
    float inter = __fmul_rn(ih, iw);
    float aa = __fmul_rn(__fsub_rn(a.z, a.x), __fsub_rn(a.w, a.y));
    float ab = __fmul_rn(__fsub_rn(b.z, b.x), __fsub_rn(b.w, b.y));
    float denom = fmaxf(__fsub_rn(__fadd_rn(aa, ab), inter), 1e-8f);
    return (double)inter >= MID * (double)denom;
}

// ---------------- K3: chunked lazy greedy NMS ----------------
// Same selection function as the literal scan transliteration (proven
// bit-identical R5 == R1/R2). New: double-buffered chunk prefetch (warp 1),
// per-warp suppression slots + __reduce_or_sync (2 barriers/chunk), smem
// broadcast in resolve, single final write-out. PRE % 32 == 0 (no tail).
__global__ void __launch_bounds__(1024, 1) nms_kernel(float* __restrict__ out) {
    const int b = blockIdx.x;
    const int tid = threadIdx.x;
    const int wid = tid >> 5;
    const int lane = tid & 31;
    const float4* sb = g_sorted + b * PRE;
    float* ob = out + (size_t)b * POST * 4;

    __shared__ float4 sel[POST];
    __shared__ float4 cand[2][32];
    __shared__ unsigned supp_w[32];
    __shared__ int sh_nsel;

    if (tid < 32) cand[0][tid] = sb[tid];
    if (tid == 0) sh_nsel = 0;
    __syncthreads();
    int nsel = 0;

    const int NCH = PRE / 32;  // 375
    for (int ch = 0; ch < NCH && nsel < POST; ch++) {
        int cur = ch & 1, nxt = cur ^ 1;

        // prefetch next chunk (warp 1) — overlaps with parallel phase
        if (wid == 1) {
            int j1 = (ch + 1) * 32;
            if (j1 < PRE) cand[nxt][lane] = sb[j1 + lane];
        }

        // parallel phase: lane's candidate vs warp-strided slice of selected
        {
            float4 myc = cand[cur][lane];
            bool killed = false;
            for (int i = wid; i < nsel; i += 32) {
                if (!killed) killed = iou_gt(myc, sel[i]);
            }
            unsigned kb = __ballot_sync(0xFFFFFFFFu, killed);
            if (lane == 0) supp_w[wid] = kb;
        }
        __syncthreads();

        // resolve phase (warp 0): OR the 32 warp slots, then pick/suppress
        if (tid < 32) {
            unsigned supp = __reduce_or_sync(0xFFFFFFFFu, supp_w[tid]);
            float4 myc = cand[cur][tid];
            unsigned live = ~supp;
            int ns = nsel;
            while (live != 0u && ns < POST) {
                int c = __ffs(live) - 1;
                float4 cb = cand[cur][c];        // smem broadcast
                live &= ~(1u << c);
                bool kill = ((live >> tid) & 1u) && iou_gt(myc, cb);
                live &= ~__ballot_sync(0xFFFFFFFFu, kill);
                if (tid == c) sel[ns] = myc;     // owner stores
                ns++;
            }
            if (tid == 0) sh_nsel = ns;
        }
        __syncthreads();
        nsel = sh_nsel;
    }

    // final write-out: clamped selected rows, zeros after exhaustion
    for (int r = tid; r < POST; r += 1024) {
        float4 v = make_float4(0.f, 0.f, 0.f, 0.f);
        if (r < nsel) v = sel[r];
        v.x = fminf(fmaxf(v.x, 0.f), 1.f);
        v.y = fminf(fmaxf(v.y, 0.f), 1.f);
        v.z = fminf(fmaxf(v.z, 0.f), 1.f);
        v.w = fminf(fmaxf(v.w, 0.f), 1.f);
        reinterpret_cast<float4*>(ob)[r] = v;
    }
}

// ---------------- launcher ----------------
extern "C" void kernel_launch(void* const* d_in, const int* in_sizes, int n_in,
                              void* d_out, int out_size) {
    const float4* boxes = (const float4*)d_in[0];   // [B, A, 4] f32
    const float4* labels = (const float4*)d_in[1];  // [B, A, 4] f32
    float* out = (float*)d_out;                     // [B, POST, 4] f32

    size_t smem = (size_t)PCAP * 8 + (size_t)NBUCK * 4;
    cudaFuncSetAttribute(select_kernel, cudaFuncAttributeMaxDynamicSharedMemorySize,
                         (int)smem);

    score_kernel<<<(BATCH * NA + 255) / 256, 256>>>(labels);
    select_kernel<<<BATCH, 1024, smem>>>(boxes);
    nms_kernel<<<BATCH, 1024>>>(out);
}